// round 1
// baseline (speedup 1.0000x reference)
#include <cuda_runtime.h>
#include <math.h>
#include <stdint.h>

// Problem constants
constexpr int B_   = 32;
constexpr int C_   = 256;
constexpr int N_   = 1024;   // H*W
constexpr int C3_  = 768;    // 3*C
constexpr int MTOT = B_ * N_; // 32768

// ---------------- scratch (static device globals; no cudaMalloc allowed) ----
__device__ float g_mean[C_];
__device__ float g_rstd[C_];
__device__ float g_t  [(size_t)MTOT * C_];   // normalized, [B,N,C]   33.5 MB
__device__ float g_kqv[(size_t)MTOT * C3_];  // [B,N,3C]             100.7 MB
__device__ float g_s  [(size_t)B_ * N_ * N_];// scores [B,N,N]        134 MB
__device__ float g_o  [(size_t)MTOT * C_];   // attn output [B,N,C]   33.5 MB
__device__ float g_po [(size_t)MTOT * C_];   // proj output [B,N,C]   33.5 MB

// ---------------- 1) BatchNorm statistics: one block per channel -----------
__global__ void bn_stats_kernel(const float* __restrict__ x) {
    const int c   = blockIdx.x;
    const int tid = threadIdx.x;
    float s = 0.f, ss = 0.f;
    // per channel: 32 batches x 1024 positions; coalesced over position
    for (int i = tid; i < B_ * N_; i += 256) {
        int b = i >> 10;
        int p = i & 1023;
        float v = x[(size_t)b * C_ * N_ + (size_t)c * N_ + p];
        s += v;
        ss += v * v;
    }
    __shared__ float sh1[256];
    __shared__ float sh2[256];
    sh1[tid] = s; sh2[tid] = ss;
    __syncthreads();
    for (int k = 128; k > 0; k >>= 1) {
        if (tid < k) { sh1[tid] += sh1[tid + k]; sh2[tid] += sh2[tid + k]; }
        __syncthreads();
    }
    if (tid == 0) {
        const float inv_n = 1.0f / (float)(B_ * N_);
        float mean = sh1[0] * inv_n;
        float var  = sh2[0] * inv_n - mean * mean;
        g_mean[c] = mean;
        g_rstd[c] = rsqrtf(var + 1e-5f);
    }
}

// ---------------- 2) normalize + transpose [B,C,N] -> [B,N,C] ---------------
__global__ void bn_apply_transpose_kernel(const float* __restrict__ x,
                                          const float* __restrict__ gamma,
                                          const float* __restrict__ beta) {
    __shared__ float sh[32][33];
    const int b  = blockIdx.z;
    const int c0 = blockIdx.y * 32;
    const int n0 = blockIdx.x * 32;
    const int tx = threadIdx.x, ty = threadIdx.y;
    const int c = c0 + ty;
    float v = x[(size_t)b * C_ * N_ + (size_t)c * N_ + (n0 + tx)];
    v = (v - g_mean[c]) * g_rstd[c] * gamma[c] + beta[c];
    sh[ty][tx] = v;
    __syncthreads();
    // write t[b][n0+ty][c0+tx], coalesced over tx
    g_t[((size_t)b * N_ + (n0 + ty)) * C_ + (c0 + tx)] = sh[tx][ty];
}

// ---------------- generic tiled fp32 GEMM: C = alpha * A * op(B) (+bias) ----
// A: [M,K] row-major, lda
// TRANSB=true : B is [N,K] row-major (ldb), computes A*B^T
// TRANSB=false: B is [K,N] row-major (ldb), computes A*B
// 64x64 tile, TK=16, 256 threads, 4x4 micro-tile per thread.
template <bool TRANSB, bool BIAS>
__global__ __launch_bounds__(256)
void gemm_kernel(const float* __restrict__ A, const float* __restrict__ Bm,
                 const float* __restrict__ bias, float* __restrict__ C,
                 int M, int Np, int K, int lda, int ldb, int ldc,
                 long batchA, long batchB, long batchC, float alpha) {
    constexpr int TM = 64, TN = 64, TK = 16;
    __shared__ float As[TK][TM];
    __shared__ float Bs[TK][TN];

    const int bz = blockIdx.z;
    const float* Ab = A  + (size_t)bz * batchA;
    const float* Bb = Bm + (size_t)bz * batchB;
    float*       Cb = C  + (size_t)bz * batchC;

    const int m0  = blockIdx.y * TM;
    const int n0  = blockIdx.x * TN;
    const int tid = threadIdx.x;
    const int txn = tid & 15;   // 0..15 -> 4 output cols
    const int tym = tid >> 4;   // 0..15 -> 4 output rows

    float acc[4][4] = {};

    for (int k0 = 0; k0 < K; k0 += TK) {
        // load A tile (64x16), 4 elems/thread, coalesced along K (16 floats/row)
        #pragma unroll
        for (int j = 0; j < 4; j++) {
            int i  = tid + j * 256;
            int kk = i & 15, mm = i >> 4;
            As[kk][mm] = Ab[(size_t)(m0 + mm) * lda + (k0 + kk)];
        }
        // load B tile
        #pragma unroll
        for (int j = 0; j < 4; j++) {
            int i = tid + j * 256;
            if (TRANSB) {
                int kk = i & 15, nn = i >> 4;
                Bs[kk][nn] = Bb[(size_t)(n0 + nn) * ldb + (k0 + kk)];
            } else {
                int nn = i & 63, kk = i >> 6;
                Bs[kk][nn] = Bb[(size_t)(k0 + kk) * ldb + (n0 + nn)];
            }
        }
        __syncthreads();

        #pragma unroll
        for (int kk = 0; kk < TK; kk++) {
            float a[4], bb[4];
            #pragma unroll
            for (int r = 0; r < 4; r++) a[r]  = As[kk][tym * 4 + r];
            #pragma unroll
            for (int s = 0; s < 4; s++) bb[s] = Bs[kk][txn * 4 + s];
            #pragma unroll
            for (int r = 0; r < 4; r++)
                #pragma unroll
                for (int s = 0; s < 4; s++)
                    acc[r][s] = fmaf(a[r], bb[s], acc[r][s]);
        }
        __syncthreads();
    }

    #pragma unroll
    for (int r = 0; r < 4; r++) {
        int m = m0 + tym * 4 + r;
        #pragma unroll
        for (int s = 0; s < 4; s++) {
            int n = n0 + txn * 4 + s;
            float v = acc[r][s] * alpha;
            if (BIAS) v += bias[n];
            Cb[(size_t)m * ldc + n] = v;
        }
    }
}

// ---------------- 5) row softmax over 1024 columns ---------------------------
__global__ void softmax_kernel(float* __restrict__ s) {
    const size_t row = blockIdx.x;
    float* p = s + row * (size_t)N_;
    const int tid = threadIdx.x; // 256
    float vals[4];
    float mx = -1e30f;
    #pragma unroll
    for (int j = 0; j < 4; j++) {
        vals[j] = p[tid + j * 256];
        mx = fmaxf(mx, vals[j]);
    }
    __shared__ float sh[256];
    sh[tid] = mx;
    __syncthreads();
    for (int k = 128; k > 0; k >>= 1) {
        if (tid < k) sh[tid] = fmaxf(sh[tid], sh[tid + k]);
        __syncthreads();
    }
    mx = sh[0];
    __syncthreads();
    float sum = 0.f;
    #pragma unroll
    for (int j = 0; j < 4; j++) {
        vals[j] = __expf(vals[j] - mx);
        sum += vals[j];
    }
    sh[tid] = sum;
    __syncthreads();
    for (int k = 128; k > 0; k >>= 1) {
        if (tid < k) sh[tid] += sh[tid + k];
        __syncthreads();
    }
    const float inv = 1.0f / sh[0];
    #pragma unroll
    for (int j = 0; j < 4; j++) p[tid + j * 256] = vals[j] * inv;
}

// ---------------- 8) transpose back [B,N,C] -> [B,C,N] + residual -----------
__global__ void epilogue_kernel(const float* __restrict__ x, float* __restrict__ out) {
    __shared__ float sh[32][33];
    const int b  = blockIdx.z;
    const int c0 = blockIdx.y * 32;
    const int n0 = blockIdx.x * 32;
    const int tx = threadIdx.x, ty = threadIdx.y;
    sh[ty][tx] = g_po[((size_t)b * N_ + (n0 + ty)) * C_ + (c0 + tx)];
    __syncthreads();
    size_t idx = (size_t)b * C_ * N_ + (size_t)(c0 + ty) * N_ + (n0 + tx);
    out[idx] = sh[tx][ty] + x[idx];
}

// ---------------- launch -----------------------------------------------------
extern "C" void kernel_launch(void* const* d_in, const int* in_sizes, int n_in,
                              void* d_out, int out_size) {
    const float* x      = (const float*)d_in[0];
    const float* gamma  = (const float*)d_in[1];
    const float* beta   = (const float*)d_in[2];
    const float* W_kqv  = (const float*)d_in[3];
    const float* b_kqv  = (const float*)d_in[4];
    const float* W_proj = (const float*)d_in[5];
    const float* b_proj = (const float*)d_in[6];
    float* out = (float*)d_out;

    void *pt, *pkqv, *ps, *po, *ppo;
    cudaGetSymbolAddress(&pt,   g_t);
    cudaGetSymbolAddress(&pkqv, g_kqv);
    cudaGetSymbolAddress(&ps,   g_s);
    cudaGetSymbolAddress(&po,   g_o);
    cudaGetSymbolAddress(&ppo,  g_po);
    float* t   = (float*)pt;
    float* kqv = (float*)pkqv;
    float* s   = (float*)ps;
    float* o   = (float*)po;
    float* po_ = (float*)ppo;

    // 1) BN stats
    bn_stats_kernel<<<C_, 256>>>(x);

    // 2) normalize + transpose to [B,N,C]
    bn_apply_transpose_kernel<<<dim3(N_ / 32, C_ / 32, B_), dim3(32, 32)>>>(x, gamma, beta);

    // 3) kqv = t @ W_kqv^T + b_kqv : [32768,256] x [768,256]^T -> [32768,768]
    gemm_kernel<true, true><<<dim3(C3_ / 64, MTOT / 64, 1), 256>>>(
        t, W_kqv, b_kqv, kqv,
        MTOT, C3_, C_, C_, C_, C3_,
        0L, 0L, 0L, 1.0f);

    // 4) s = q @ k^T / 16 per batch : [1024,256] x [1024,256]^T
    gemm_kernel<true, false><<<dim3(N_ / 64, N_ / 64, B_), 256>>>(
        kqv /*q*/, kqv + 256 /*k*/, nullptr, s,
        N_, N_, C_, C3_, C3_, N_,
        (long)N_ * C3_, (long)N_ * C3_, (long)N_ * N_, 0.0625f);

    // 5) softmax along rows
    softmax_kernel<<<B_ * N_, 256>>>(s);

    // 6) o = attn @ v per batch : [1024,1024] x [1024,256]
    gemm_kernel<false, false><<<dim3(C_ / 64, N_ / 64, B_), 256>>>(
        s, kqv + 512 /*v*/, nullptr, o,
        N_, C_, N_, N_, C3_, C_,
        (long)N_ * N_, (long)N_ * C3_, (long)N_ * C_, 1.0f);

    // 7) po = o @ W_proj^T + b_proj : [32768,256] x [256,256]^T
    gemm_kernel<true, true><<<dim3(C_ / 64, MTOT / 64, 1), 256>>>(
        o, W_proj, b_proj, po_,
        MTOT, C_, C_, C_, C_, C_,
        0L, 0L, 0L, 1.0f);

    // 8) transpose back + residual
    epilogue_kernel<<<dim3(N_ / 32, C_ / 32, B_), dim3(32, 32)>>>(x, out);
}

// round 3
// speedup vs baseline: 4.2637x; 4.2637x over previous
#include <cuda_runtime.h>
#include <math.h>
#include <stdint.h>

// ---------------- problem constants ----------------
constexpr int B_   = 32;
constexpr int C_   = 256;
constexpr int N_   = 1024;
constexpr int C3_  = 768;
constexpr int MTOT = B_ * N_;   // 32768

// ---------------- scratch ----------------
__device__ float g_mean[C_];
__device__ float g_rstd[C_];
__device__ float g_t  [(size_t)MTOT * C_];    // [B,N,C]
__device__ float g_kqv[(size_t)MTOT * C3_];   // [B,N,3C]
__device__ float g_s  [(size_t)B_ * N_ * N_]; // [B,N,N]
__device__ float g_vt [(size_t)B_ * C_ * N_]; // [B,C,N]  (v transposed)
__device__ float g_o  [(size_t)MTOT * C_];    // [B,N,C]
__device__ float g_po [(size_t)MTOT * C_];    // [B,N,C]

// ---------------- small PTX helpers ----------------
__device__ __forceinline__ uint32_t smem_u32(const void* p) {
    return (uint32_t)__cvta_generic_to_shared(p);
}
__device__ __forceinline__ uint32_t f2tf32(float f) {
    uint32_t r;
    asm("cvt.rna.tf32.f32 %0, %1;" : "=r"(r) : "f"(f));
    return r;
}
__device__ __forceinline__ void mma_tf32(float c[4], const uint32_t a[4], const uint32_t b[2]) {
    asm volatile(
        "mma.sync.aligned.m16n8k8.row.col.f32.tf32.tf32.f32 "
        "{%0,%1,%2,%3}, {%4,%5,%6,%7}, {%8,%9}, {%0,%1,%2,%3};"
        : "+f"(c[0]), "+f"(c[1]), "+f"(c[2]), "+f"(c[3])
        : "r"(a[0]), "r"(a[1]), "r"(a[2]), "r"(a[3]), "r"(b[0]), "r"(b[1]));
}
#define CP_ASYNC16(dst, src) \
    asm volatile("cp.async.cg.shared.global [%0], [%1], 16;" :: "r"(dst), "l"(src))
#define CP_ASYNC_COMMIT() asm volatile("cp.async.commit_group;" ::: "memory")
#define CP_ASYNC_WAIT(n)  asm volatile("cp.async.wait_group %0;" :: "n"(n) : "memory")

// ---------------- tf32 tensor-core GEMM: C = alpha * A * B^T (+bias) -------
// A [M,K] row-major (lda), B [N,K] row-major (ldb).
// CTA tile 128x128, K-chunk 32, 256 threads = 2(M) x 4(N) warps,
// warp tile 64x32 -> 4x4 m16n8k8 MMAs per k8-step.
constexpr int STAGES      = 3;
constexpr int ROW_F       = 36;                    // padded row stride (floats)
constexpr int TILE_FLOATS = 128 * ROW_F;           // one operand tile
constexpr int STAGE_FLOATS= 2 * TILE_FLOATS;       // A + B
constexpr int SMEM_DYN    = STAGES * STAGE_FLOATS * 4;  // 110592 B

template <bool BIAS>
__global__ __launch_bounds__(256)
void tc_gemm(const float* __restrict__ A, const float* __restrict__ Bm,
             const float* __restrict__ bias, float* __restrict__ Cm,
             int K, int lda, int ldb, int ldc,
             long sA, long sB, long sC, float alpha) {
    extern __shared__ float sm[];

    const int tid  = threadIdx.x;
    const int lane = tid & 31;
    const int warp = tid >> 5;
    const int wm   = warp & 1;          // 0..1  (M)
    const int wn   = warp >> 1;         // 0..3  (N)
    const int g    = lane >> 2;         // 0..7
    const int q    = lane & 3;          // 0..3

    const int m0 = blockIdx.y * 128;
    const int n0 = blockIdx.x * 128;
    const float* Ab = A  + (size_t)blockIdx.z * sA;
    const float* Bb = Bm + (size_t)blockIdx.z * sB;
    float*       Cb = Cm + (size_t)blockIdx.z * sC;

    const uint32_t smb = smem_u32(sm);

    // stage loader: 128x32 floats each for A and B; 4 float4 per thread per tile
    auto load_stage = [&](int slot, int kc) {
        const uint32_t abase = smb + slot * STAGE_FLOATS * 4;
        const uint32_t bbase = abase + TILE_FLOATS * 4;
        const float* Asrc = Ab + (size_t)m0 * lda + kc * 32;
        const float* Bsrc = Bb + (size_t)n0 * ldb + kc * 32;
        #pragma unroll
        for (int j = 0; j < 4; j++) {
            int i   = tid + j * 256;
            int row = i >> 3;
            int kg  = i & 7;
            CP_ASYNC16(abase + (uint32_t)(row * ROW_F * 4 + kg * 16),
                       Asrc + (size_t)row * lda + kg * 4);
            CP_ASYNC16(bbase + (uint32_t)(row * ROW_F * 4 + kg * 16),
                       Bsrc + (size_t)row * ldb + kg * 4);
        }
        CP_ASYNC_COMMIT();
    };

    float acc[4][4][4] = {};
    const int nk = K >> 5;

    load_stage(0, 0);
    load_stage(1, 1);

    for (int ks = 0; ks < nk; ks++) {
        const int s = ks % STAGES;
        CP_ASYNC_WAIT(STAGES - 2);
        __syncthreads();

        // prefetch next stage into the buffer consumed at ks-1
        const int next = ks + STAGES - 1;
        if (next < nk) load_stage(next % STAGES, next);
        else           CP_ASYNC_COMMIT();   // keep group accounting uniform

        const float* Asm = sm + s * STAGE_FLOATS;
        const float* Bsm = Asm + TILE_FLOATS;

        #pragma unroll
        for (int k8 = 0; k8 < 32; k8 += 8) {
            uint32_t af[4][4], bf[4][2];
            #pragma unroll
            for (int tm = 0; tm < 4; tm++) {
                const float* pa = Asm + (wm * 64 + tm * 16 + g) * ROW_F + k8 + q;
                af[tm][0] = f2tf32(pa[0]);
                af[tm][1] = f2tf32(pa[8 * ROW_F]);
                af[tm][2] = f2tf32(pa[4]);
                af[tm][3] = f2tf32(pa[8 * ROW_F + 4]);
            }
            #pragma unroll
            for (int tn = 0; tn < 4; tn++) {
                const float* pb = Bsm + (wn * 32 + tn * 8 + g) * ROW_F + k8 + q;
                bf[tn][0] = f2tf32(pb[0]);
                bf[tn][1] = f2tf32(pb[4]);
            }
            #pragma unroll
            for (int tm = 0; tm < 4; tm++)
                #pragma unroll
                for (int tn = 0; tn < 4; tn++)
                    mma_tf32(acc[tm][tn], af[tm], bf[tn]);
        }
    }

    // epilogue: write accumulators (c0,c1 row g; c2,c3 row g+8; cols 2q,2q+1)
    #pragma unroll
    for (int tm = 0; tm < 4; tm++) {
        const int row = m0 + wm * 64 + tm * 16 + g;
        #pragma unroll
        for (int tn = 0; tn < 4; tn++) {
            const int col = n0 + wn * 32 + tn * 8 + 2 * q;
            float b0 = 0.f, b1 = 0.f;
            if (BIAS) { b0 = __ldg(&bias[col]); b1 = __ldg(&bias[col + 1]); }
            float2 v0, v1;
            v0.x = acc[tm][tn][0] * alpha + b0;
            v0.y = acc[tm][tn][1] * alpha + b1;
            v1.x = acc[tm][tn][2] * alpha + b0;
            v1.y = acc[tm][tn][3] * alpha + b1;
            *reinterpret_cast<float2*>(&Cb[(size_t)row * ldc + col])       = v0;
            *reinterpret_cast<float2*>(&Cb[(size_t)(row + 8) * ldc + col]) = v1;
        }
    }
}

// ---------------- BN stats ----------------
__global__ void bn_stats_kernel(const float* __restrict__ x) {
    const int c = blockIdx.x, tid = threadIdx.x;
    float s = 0.f, ss = 0.f;
    for (int i = tid; i < B_ * N_; i += 256) {
        int b = i >> 10, p = i & 1023;
        float v = x[(size_t)b * C_ * N_ + (size_t)c * N_ + p];
        s += v; ss += v * v;
    }
    __shared__ float sh1[256], sh2[256];
    sh1[tid] = s; sh2[tid] = ss;
    __syncthreads();
    for (int k = 128; k > 0; k >>= 1) {
        if (tid < k) { sh1[tid] += sh1[tid + k]; sh2[tid] += sh2[tid + k]; }
        __syncthreads();
    }
    if (tid == 0) {
        const float inv_n = 1.0f / (float)(B_ * N_);
        float mean = sh1[0] * inv_n;
        float var  = sh2[0] * inv_n - mean * mean;
        g_mean[c] = mean;
        g_rstd[c] = rsqrtf(var + 1e-5f);
    }
}

// ---------------- BN apply + transpose [B,C,N] -> [B,N,C] ----------------
__global__ void bn_apply_transpose_kernel(const float* __restrict__ x,
                                          const float* __restrict__ gamma,
                                          const float* __restrict__ beta) {
    __shared__ float sh[32][33];
    const int b = blockIdx.z, c0 = blockIdx.y * 32, n0 = blockIdx.x * 32;
    const int tx = threadIdx.x, ty = threadIdx.y;
    const int c = c0 + ty;
    float v = x[(size_t)b * C_ * N_ + (size_t)c * N_ + (n0 + tx)];
    v = (v - g_mean[c]) * g_rstd[c] * gamma[c] + beta[c];
    sh[ty][tx] = v;
    __syncthreads();
    g_t[((size_t)b * N_ + (n0 + ty)) * C_ + (c0 + tx)] = sh[tx][ty];
}

// ---------------- V transpose: kqv[:, :, 512:768] -> vt [B,C,N] ----------
__global__ void v_transpose_kernel() {
    __shared__ float sh[32][33];
    const int b = blockIdx.z, c0 = blockIdx.y * 32, n0 = blockIdx.x * 32;
    const int tx = threadIdx.x, ty = threadIdx.y;
    sh[ty][tx] = g_kqv[((size_t)b * N_ + (n0 + ty)) * C3_ + 512 + c0 + tx];
    __syncthreads();
    g_vt[((size_t)b * C_ + (c0 + ty)) * N_ + (n0 + tx)] = sh[tx][ty];
}

// ---------------- softmax over rows of 1024 ----------------
__global__ void softmax_kernel(float* __restrict__ s) {
    const size_t row = blockIdx.x;
    float* p = s + row * (size_t)N_;
    const int tid = threadIdx.x;
    float vals[4];
    float mx = -1e30f;
    #pragma unroll
    for (int j = 0; j < 4; j++) { vals[j] = p[tid + j * 256]; mx = fmaxf(mx, vals[j]); }
    __shared__ float sh[256];
    sh[tid] = mx; __syncthreads();
    for (int k = 128; k > 0; k >>= 1) {
        if (tid < k) sh[tid] = fmaxf(sh[tid], sh[tid + k]);
        __syncthreads();
    }
    mx = sh[0]; __syncthreads();
    float sum = 0.f;
    #pragma unroll
    for (int j = 0; j < 4; j++) { vals[j] = __expf(vals[j] - mx); sum += vals[j]; }
    sh[tid] = sum; __syncthreads();
    for (int k = 128; k > 0; k >>= 1) {
        if (tid < k) sh[tid] += sh[tid + k];
        __syncthreads();
    }
    const float inv = 1.0f / sh[0];
    #pragma unroll
    for (int j = 0; j < 4; j++) p[tid + j * 256] = vals[j] * inv;
}

// ---------------- final: transpose back + residual ----------------
__global__ void epilogue_kernel(const float* __restrict__ x, float* __restrict__ out) {
    __shared__ float sh[32][33];
    const int b = blockIdx.z, c0 = blockIdx.y * 32, n0 = blockIdx.x * 32;
    const int tx = threadIdx.x, ty = threadIdx.y;
    sh[ty][tx] = g_po[((size_t)b * N_ + (n0 + ty)) * C_ + (c0 + tx)];
    __syncthreads();
    size_t idx = (size_t)b * C_ * N_ + (size_t)(c0 + ty) * N_ + (n0 + tx);
    out[idx] = sh[tx][ty] + x[idx];
}

// ---------------- launch ----------------
extern "C" void kernel_launch(void* const* d_in, const int* in_sizes, int n_in,
                              void* d_out, int out_size) {
    const float* x      = (const float*)d_in[0];
    const float* gamma  = (const float*)d_in[1];
    const float* beta   = (const float*)d_in[2];
    const float* W_kqv  = (const float*)d_in[3];
    const float* b_kqv  = (const float*)d_in[4];
    const float* W_proj = (const float*)d_in[5];
    const float* b_proj = (const float*)d_in[6];
    float* out = (float*)d_out;

    cudaFuncSetAttribute(tc_gemm<true>,  cudaFuncAttributeMaxDynamicSharedMemorySize, SMEM_DYN);
    cudaFuncSetAttribute(tc_gemm<false>, cudaFuncAttributeMaxDynamicSharedMemorySize, SMEM_DYN);

    void *pt, *pkqv, *ps, *pvt, *po, *ppo;
    cudaGetSymbolAddress(&pt,   g_t);
    cudaGetSymbolAddress(&pkqv, g_kqv);
    cudaGetSymbolAddress(&ps,   g_s);
    cudaGetSymbolAddress(&pvt,  g_vt);
    cudaGetSymbolAddress(&po,   g_o);
    cudaGetSymbolAddress(&ppo,  g_po);
    float* t   = (float*)pt;
    float* kqv = (float*)pkqv;
    float* s   = (float*)ps;
    float* vt  = (float*)pvt;
    float* o   = (float*)po;
    float* po_ = (float*)ppo;

    bn_stats_kernel<<<C_, 256>>>(x);
    bn_apply_transpose_kernel<<<dim3(N_ / 32, C_ / 32, B_), dim3(32, 32)>>>(x, gamma, beta);

    // kqv = t @ W_kqv^T + b_kqv : [32768,256] x [768,256]^T
    tc_gemm<true><<<dim3(C3_ / 128, MTOT / 128, 1), 256, SMEM_DYN>>>(
        t, W_kqv, b_kqv, kqv, C_, C_, C_, C3_, 0L, 0L, 0L, 1.0f);

    // s = q @ k^T / 16 per batch : [1024,256] x [1024,256]^T
    tc_gemm<false><<<dim3(N_ / 128, N_ / 128, B_), 256, SMEM_DYN>>>(
        kqv, kqv + 256, nullptr, s, C_, C3_, C3_, N_,
        (long)N_ * C3_, (long)N_ * C3_, (long)N_ * N_, 0.0625f);

    softmax_kernel<<<B_ * N_, 256>>>(s);

    v_transpose_kernel<<<dim3(N_ / 32, C_ / 32, B_), dim3(32, 32)>>>();

    // o = attn @ v : A = s [1024,1024], B = vt [256,1024] (as B^T)
    tc_gemm<false><<<dim3(C_ / 128, N_ / 128, B_), 256, SMEM_DYN>>>(
        s, vt, nullptr, o, N_, N_, N_, C_,
        (long)N_ * N_, (long)C_ * N_, (long)N_ * C_, 1.0f);

    // po = o @ W_proj^T + b_proj : [32768,256] x [256,256]^T
    tc_gemm<true><<<dim3(C_ / 128, MTOT / 128, 1), 256, SMEM_DYN>>>(
        o, W_proj, b_proj, po_, C_, C_, C_, C_, 0L, 0L, 0L, 1.0f);

    epilogue_kernel<<<dim3(N_ / 32, C_ / 32, B_), dim3(32, 32)>>>(x, out);
}

// round 4
// speedup vs baseline: 5.1830x; 1.2156x over previous
#include <cuda_runtime.h>
#include <math.h>
#include <stdint.h>

// ---------------- problem constants ----------------
constexpr int B_   = 32;
constexpr int C_   = 256;
constexpr int N_   = 1024;
constexpr int C3_  = 768;
constexpr int MTOT = B_ * N_;   // 32768

// ---------------- scratch ----------------
__device__ float g_mean[C_];
__device__ float g_rstd[C_];
__device__ float g_t  [(size_t)MTOT * C_];    // [B,N,C]   (tf32-rounded)
__device__ float g_kqv[(size_t)MTOT * C3_];   // [B,N,3C]  (tf32-rounded)
__device__ float g_s  [(size_t)B_ * N_ * N_]; // [B,N,N]   (scores / probs)
__device__ float g_o  [(size_t)MTOT * C_];    // [B,N,C]   (tf32-rounded)
__device__ float g_po [(size_t)MTOT * C_];    // [B,N,C]

// ---------------- small PTX helpers ----------------
__device__ __forceinline__ uint32_t smem_u32(const void* p) {
    return (uint32_t)__cvta_generic_to_shared(p);
}
__device__ __forceinline__ float round_tf32(float f) {
    uint32_t r;
    asm("cvt.rna.tf32.f32 %0, %1;" : "=r"(r) : "f"(f));
    return __uint_as_float(r);
}
__device__ __forceinline__ void mma_tf32(float c[4], const uint32_t a[4], const uint32_t b[2]) {
    asm volatile(
        "mma.sync.aligned.m16n8k8.row.col.f32.tf32.tf32.f32 "
        "{%0,%1,%2,%3}, {%4,%5,%6,%7}, {%8,%9}, {%0,%1,%2,%3};"
        : "+f"(c[0]), "+f"(c[1]), "+f"(c[2]), "+f"(c[3])
        : "r"(a[0]), "r"(a[1]), "r"(a[2]), "r"(a[3]), "r"(b[0]), "r"(b[1]));
}
#define CP_ASYNC16(dst, src) \
    asm volatile("cp.async.cg.shared.global [%0], [%1], 16;" :: "r"(dst), "l"(src))
#define CP_ASYNC_COMMIT() asm volatile("cp.async.commit_group;" ::: "memory")
#define CP_ASYNC_WAIT(n)  asm volatile("cp.async.wait_group %0;" :: "n"(n) : "memory")

// ---------------- tf32 tensor-core GEMM --------------------------------
// C = alpha * A * op(B) (+bias), all inputs already tf32-rounded fp32 bits.
// A [M,K] row-major (lda).
// BT=true : B [N,K] row-major (ldb)  (weights / K-operand; computes A*B^T)
// BT=false: B [K,N] row-major (ldb)  (V-operand; computes A*B)
// CTA tile 128x128, K-chunk 32, 256 threads = 2(M) x 4(N) warps,
// warp tile 64x32 -> 4x4 m16n8k8 MMAs per k8-step. 2-stage cp.async pipe.
constexpr int ROW_A   = 36;                      // A tile row stride (floats)
constexpr int ROW_BT  = 36;                      // B tile stride, BT=true
constexpr int ROW_BN  = 136;                     // B tile stride, BT=false ([32][136])
constexpr int A_FLOATS  = 128 * ROW_A;           // 4608
constexpr int BT_FLOATS = 128 * ROW_BT;          // 4608
constexpr int BN_FLOATS = 32 * ROW_BN;           // 4352
// stage = A + max(B variants); use worst case for both instantiations
constexpr int STAGE_FLOATS = A_FLOATS + BT_FLOATS;       // 9216 floats
constexpr int SMEM_DYN     = 2 * STAGE_FLOATS * 4;       // 73728 B

template <bool BT, bool BIAS>
__global__ __launch_bounds__(256, 2)
void tc_gemm(const float* __restrict__ A, const float* __restrict__ Bm,
             const float* __restrict__ bias, float* __restrict__ Cm,
             int K, int lda, int ldb, int ldc,
             long sA, long sB, long sC, float alpha, bool round_out) {
    extern __shared__ float sm[];

    const int tid  = threadIdx.x;
    const int lane = tid & 31;
    const int warp = tid >> 5;
    const int wm   = warp & 1;          // 0..1  (M)
    const int wn   = warp >> 1;         // 0..3  (N)
    const int g    = lane >> 2;         // 0..7
    const int q    = lane & 3;          // 0..3

    const int m0 = blockIdx.y * 128;
    const int n0 = blockIdx.x * 128;
    const float* Ab = A  + (size_t)blockIdx.z * sA;
    const float* Bb = Bm + (size_t)blockIdx.z * sB;
    float*       Cb = Cm + (size_t)blockIdx.z * sC;

    const uint32_t smb = smem_u32(sm);

    auto load_stage = [&](int slot, int kc) {
        const uint32_t abase = smb + slot * STAGE_FLOATS * 4;
        const uint32_t bbase = abase + A_FLOATS * 4;
        const float* Asrc = Ab + (size_t)m0 * lda + kc * 32;
        #pragma unroll
        for (int j = 0; j < 4; j++) {
            int i   = tid + j * 256;
            int row = i >> 3;
            int kg  = i & 7;
            CP_ASYNC16(abase + (uint32_t)(row * ROW_A * 4 + kg * 16),
                       Asrc + (size_t)row * lda + kg * 4);
        }
        if (BT) {
            const float* Bsrc = Bb + (size_t)n0 * ldb + kc * 32;
            #pragma unroll
            for (int j = 0; j < 4; j++) {
                int i   = tid + j * 256;
                int row = i >> 3;
                int kg  = i & 7;
                CP_ASYNC16(bbase + (uint32_t)(row * ROW_BT * 4 + kg * 16),
                           Bsrc + (size_t)row * ldb + kg * 4);
            }
        } else {
            // B tile: 32 k-rows x 128 n-cols
            const float* Bsrc = Bb + (size_t)(kc * 32) * ldb + n0;
            #pragma unroll
            for (int j = 0; j < 4; j++) {
                int i   = tid + j * 256;
                int row = i >> 5;         // 0..31 (k)
                int c4  = i & 31;         // 0..31 (n in float4s)
                CP_ASYNC16(bbase + (uint32_t)(row * ROW_BN * 4 + c4 * 16),
                           Bsrc + (size_t)row * ldb + c4 * 4);
            }
        }
        CP_ASYNC_COMMIT();
    };

    float acc[4][4][4] = {};
    const int nk = K >> 5;

    load_stage(0, 0);

    for (int ks = 0; ks < nk; ks++) {
        if (ks + 1 < nk) load_stage((ks + 1) & 1, ks + 1);
        else             CP_ASYNC_COMMIT();
        CP_ASYNC_WAIT(1);                 // stage ks resident
        __syncthreads();

        const float* Asm = sm + (ks & 1) * STAGE_FLOATS;
        const float* Bsm = Asm + A_FLOATS;

        #pragma unroll
        for (int k8 = 0; k8 < 32; k8 += 8) {
            uint32_t af[4][4], bf[4][2];
            #pragma unroll
            for (int tm = 0; tm < 4; tm++) {
                const float* pa = Asm + (wm * 64 + tm * 16 + g) * ROW_A + k8 + q;
                af[tm][0] = __float_as_uint(pa[0]);
                af[tm][1] = __float_as_uint(pa[8 * ROW_A]);
                af[tm][2] = __float_as_uint(pa[4]);
                af[tm][3] = __float_as_uint(pa[8 * ROW_A + 4]);
            }
            #pragma unroll
            for (int tn = 0; tn < 4; tn++) {
                if (BT) {
                    const float* pb = Bsm + (wn * 32 + tn * 8 + g) * ROW_BT + k8 + q;
                    bf[tn][0] = __float_as_uint(pb[0]);
                    bf[tn][1] = __float_as_uint(pb[4]);
                } else {
                    const float* pb = Bsm + (k8 + q) * ROW_BN + wn * 32 + tn * 8 + g;
                    bf[tn][0] = __float_as_uint(pb[0]);
                    bf[tn][1] = __float_as_uint(pb[4 * ROW_BN]);
                }
            }
            #pragma unroll
            for (int tm = 0; tm < 4; tm++)
                #pragma unroll
                for (int tn = 0; tn < 4; tn++)
                    mma_tf32(acc[tm][tn], af[tm], bf[tn]);
        }
        __syncthreads();
    }

    // epilogue: (c0,c1)=row g, (c2,c3)=row g+8; cols 2q, 2q+1
    #pragma unroll
    for (int tm = 0; tm < 4; tm++) {
        const int row = m0 + wm * 64 + tm * 16 + g;
        #pragma unroll
        for (int tn = 0; tn < 4; tn++) {
            const int col = n0 + wn * 32 + tn * 8 + 2 * q;
            float b0 = 0.f, b1 = 0.f;
            if (BIAS) { b0 = __ldg(&bias[col]); b1 = __ldg(&bias[col + 1]); }
            float2 v0, v1;
            v0.x = acc[tm][tn][0] * alpha + b0;
            v0.y = acc[tm][tn][1] * alpha + b1;
            v1.x = acc[tm][tn][2] * alpha + b0;
            v1.y = acc[tm][tn][3] * alpha + b1;
            if (round_out) {
                v0.x = round_tf32(v0.x); v0.y = round_tf32(v0.y);
                v1.x = round_tf32(v1.x); v1.y = round_tf32(v1.y);
            }
            *reinterpret_cast<float2*>(&Cb[(size_t)row * ldc + col])       = v0;
            *reinterpret_cast<float2*>(&Cb[(size_t)(row + 8) * ldc + col]) = v1;
        }
    }
}

// ---------------- BN stats ----------------
__global__ void bn_stats_kernel(const float* __restrict__ x) {
    const int c = blockIdx.x, tid = threadIdx.x;
    float s = 0.f, ss = 0.f;
    for (int i = tid; i < B_ * N_; i += 256) {
        int b = i >> 10, p = i & 1023;
        float v = x[(size_t)b * C_ * N_ + (size_t)c * N_ + p];
        s += v; ss += v * v;
    }
    __shared__ float sh1[256], sh2[256];
    sh1[tid] = s; sh2[tid] = ss;
    __syncthreads();
    for (int k = 128; k > 0; k >>= 1) {
        if (tid < k) { sh1[tid] += sh1[tid + k]; sh2[tid] += sh2[tid + k]; }
        __syncthreads();
    }
    if (tid == 0) {
        const float inv_n = 1.0f / (float)(B_ * N_);
        float mean = sh1[0] * inv_n;
        float var  = sh2[0] * inv_n - mean * mean;
        g_mean[c] = mean;
        g_rstd[c] = rsqrtf(var + 1e-5f);
    }
}

// ------- BN apply + transpose [B,C,N] -> [B,N,C], tf32-rounded -----------
__global__ void bn_apply_transpose_kernel(const float* __restrict__ x,
                                          const float* __restrict__ gamma,
                                          const float* __restrict__ beta) {
    __shared__ float sh[32][33];
    const int b = blockIdx.z, c0 = blockIdx.y * 32, n0 = blockIdx.x * 32;
    const int tx = threadIdx.x, ty = threadIdx.y;
    const int c = c0 + ty;
    float v = x[(size_t)b * C_ * N_ + (size_t)c * N_ + (n0 + tx)];
    v = (v - g_mean[c]) * g_rstd[c] * gamma[c] + beta[c];
    sh[ty][tx] = round_tf32(v);
    __syncthreads();
    g_t[((size_t)b * N_ + (n0 + ty)) * C_ + (c0 + tx)] = sh[tx][ty];
}

// ---------------- softmax over rows of 1024 (float4, warp-shuffle) --------
__global__ void softmax_kernel(float* __restrict__ s) {
    const size_t row = blockIdx.x;
    float4* p4 = reinterpret_cast<float4*>(s + row * (size_t)N_);
    const int tid  = threadIdx.x;     // 256 threads, exactly one float4 each
    const int lane = tid & 31;
    const int wid  = tid >> 5;
    __shared__ float sh[8];

    float4 v = p4[tid];
    float mx = fmaxf(fmaxf(v.x, v.y), fmaxf(v.z, v.w));
    #pragma unroll
    for (int o = 16; o > 0; o >>= 1) mx = fmaxf(mx, __shfl_xor_sync(~0u, mx, o));
    if (lane == 0) sh[wid] = mx;
    __syncthreads();
    mx = sh[0];
    #pragma unroll
    for (int w = 1; w < 8; w++) mx = fmaxf(mx, sh[w]);

    v.x = __expf(v.x - mx); v.y = __expf(v.y - mx);
    v.z = __expf(v.z - mx); v.w = __expf(v.w - mx);
    float sum = v.x + v.y + v.z + v.w;
    #pragma unroll
    for (int o = 16; o > 0; o >>= 1) sum += __shfl_xor_sync(~0u, sum, o);
    __syncthreads();
    if (lane == 0) sh[wid] = sum;
    __syncthreads();
    sum = sh[0];
    #pragma unroll
    for (int w = 1; w < 8; w++) sum += sh[w];
    const float inv = 1.0f / sum;

    v.x = round_tf32(v.x * inv); v.y = round_tf32(v.y * inv);
    v.z = round_tf32(v.z * inv); v.w = round_tf32(v.w * inv);
    p4[tid] = v;
}

// ---------------- final: transpose back + residual ----------------
__global__ void epilogue_kernel(const float* __restrict__ x, float* __restrict__ out) {
    __shared__ float sh[32][33];
    const int b = blockIdx.z, c0 = blockIdx.y * 32, n0 = blockIdx.x * 32;
    const int tx = threadIdx.x, ty = threadIdx.y;
    sh[ty][tx] = g_po[((size_t)b * N_ + (n0 + ty)) * C_ + (c0 + tx)];
    __syncthreads();
    size_t idx = (size_t)b * C_ * N_ + (size_t)(c0 + ty) * N_ + (n0 + tx);
    out[idx] = sh[tx][ty] + x[idx];
}

// ---------------- launch ----------------
extern "C" void kernel_launch(void* const* d_in, const int* in_sizes, int n_in,
                              void* d_out, int out_size) {
    const float* x      = (const float*)d_in[0];
    const float* gamma  = (const float*)d_in[1];
    const float* beta   = (const float*)d_in[2];
    const float* W_kqv  = (const float*)d_in[3];
    const float* b_kqv  = (const float*)d_in[4];
    const float* W_proj = (const float*)d_in[5];
    const float* b_proj = (const float*)d_in[6];
    float* out = (float*)d_out;

    cudaFuncSetAttribute(tc_gemm<true,  true >, cudaFuncAttributeMaxDynamicSharedMemorySize, SMEM_DYN);
    cudaFuncSetAttribute(tc_gemm<true,  false>, cudaFuncAttributeMaxDynamicSharedMemorySize, SMEM_DYN);
    cudaFuncSetAttribute(tc_gemm<false, false>, cudaFuncAttributeMaxDynamicSharedMemorySize, SMEM_DYN);

    void *pt, *pkqv, *ps, *po, *ppo;
    cudaGetSymbolAddress(&pt,   g_t);
    cudaGetSymbolAddress(&pkqv, g_kqv);
    cudaGetSymbolAddress(&ps,   g_s);
    cudaGetSymbolAddress(&po,   g_o);
    cudaGetSymbolAddress(&ppo,  g_po);
    float* t   = (float*)pt;
    float* kqv = (float*)pkqv;
    float* s   = (float*)ps;
    float* o   = (float*)po;
    float* po_ = (float*)ppo;

    bn_stats_kernel<<<C_, 256>>>(x);
    bn_apply_transpose_kernel<<<dim3(N_ / 32, C_ / 32, B_), dim3(32, 32)>>>(x, gamma, beta);

    // kqv = t @ W_kqv^T + b_kqv (outputs tf32-rounded)
    tc_gemm<true, true><<<dim3(C3_ / 128, MTOT / 128, 1), 256, SMEM_DYN>>>(
        t, W_kqv, b_kqv, kqv, C_, C_, C_, C3_, 0L, 0L, 0L, 1.0f, true);

    // s = q @ k^T / 16 per batch
    tc_gemm<true, false><<<dim3(N_ / 128, N_ / 128, B_), 256, SMEM_DYN>>>(
        kqv, kqv + 256, nullptr, s, C_, C3_, C3_, N_,
        (long)N_ * C3_, (long)N_ * C3_, (long)N_ * N_, 0.0625f, false);

    softmax_kernel<<<B_ * N_, 256>>>(s);

    // o = attn @ v : A = s [1024,1024], B = v [K=1024 rows, N=256 cols] in kqv
    tc_gemm<false, false><<<dim3(C_ / 128, N_ / 128, B_), 256, SMEM_DYN>>>(
        s, kqv + 512, nullptr, o, N_, N_, C3_, C_,
        (long)N_ * N_, (long)N_ * C3_, (long)N_ * C_, 1.0f, true);

    // po = o @ W_proj^T + b_proj
    tc_gemm<true, true><<<dim3(C_ / 128, MTOT / 128, 1), 256, SMEM_DYN>>>(
        o, W_proj, b_proj, po_, C_, C_, C_, C_, 0L, 0L, 0L, 1.0f, false);

    epilogue_kernel<<<dim3(N_ / 32, C_ / 32, B_), dim3(32, 32)>>>(x, out);
}